// round 1
// baseline (speedup 1.0000x reference)
#include <cuda_runtime.h>
#include <math.h>

// Problem constants (fixed by the reference)
#define VOCAB  100000
#define DIM    128
#define BATCH  4096
#define CTX    10
#define NNEG   200   // CTX * N_NEGS

__device__ __forceinline__ float log_sigmoid(float x) {
    // log(sigmoid(x)) = min(x,0) - log1p(exp(-|x|))
    float ax = fabsf(x);
    return fminf(x, 0.0f) - log1pf(__expf(-ax));
}

__device__ __forceinline__ float warp_dot(const float4 a, const float4 b) {
    float p = fmaf(a.x, b.x, fmaf(a.y, b.y, fmaf(a.z, b.z, a.w * b.w)));
    p += __shfl_xor_sync(0xffffffffu, p, 16);
    p += __shfl_xor_sync(0xffffffffu, p, 8);
    p += __shfl_xor_sync(0xffffffffu, p, 4);
    p += __shfl_xor_sync(0xffffffffu, p, 2);
    p += __shfl_xor_sync(0xffffffffu, p, 1);
    return p;  // full sum in every lane
}

__global__ void sgns_zero_out(float* out) { out[0] = 0.0f; }

__global__ __launch_bounds__(256, 8)
void sgns_kernel(const float* __restrict__ emb_i,
                 const float* __restrict__ emb_o,
                 const int*   __restrict__ iword,
                 const int*   __restrict__ owords,
                 const int*   __restrict__ nwords,
                 float*       __restrict__ out) {
    const int warp = (blockIdx.x * blockDim.x + threadIdx.x) >> 5;
    const int lane = threadIdx.x & 31;
    if (warp >= BATCH) return;

    // Input-word vector slice for this lane (4 floats; warp covers all 128)
    const float4 iv =
        *reinterpret_cast<const float4*>(emb_i + (size_t)iword[warp] * DIM + lane * 4);

    const int* __restrict__ ow = owords + warp * CTX;
    const int* __restrict__ nw = nwords + warp * NNEG;

    float acc = 0.0f;

    // ---- positives: 10 rows, fully unrolled (10 loads in flight) ----
    {
        float4 v[CTX];
#pragma unroll
        for (int c = 0; c < CTX; c++) {
            const float4* row =
                reinterpret_cast<const float4*>(emb_o + (size_t)ow[c] * DIM);
            v[c] = __ldg(row + lane);
        }
#pragma unroll
        for (int c = 0; c < CTX; c++) {
            acc += log_sigmoid(warp_dot(iv, v[c]));
        }
    }

    // ---- negatives: 200 rows, unroll x4 for MLP ----
    for (int k = 0; k < NNEG; k += 4) {
        int i0 = nw[k + 0], i1 = nw[k + 1], i2 = nw[k + 2], i3 = nw[k + 3];
        const float4 v0 = __ldg(reinterpret_cast<const float4*>(emb_o + (size_t)i0 * DIM) + lane);
        const float4 v1 = __ldg(reinterpret_cast<const float4*>(emb_o + (size_t)i1 * DIM) + lane);
        const float4 v2 = __ldg(reinterpret_cast<const float4*>(emb_o + (size_t)i2 * DIM) + lane);
        const float4 v3 = __ldg(reinterpret_cast<const float4*>(emb_o + (size_t)i3 * DIM) + lane);
        acc += log_sigmoid(-warp_dot(iv, v0));
        acc += log_sigmoid(-warp_dot(iv, v1));
        acc += log_sigmoid(-warp_dot(iv, v2));
        acc += log_sigmoid(-warp_dot(iv, v3));
    }

    // loss_b = -(mean_c oloss + mean_c nloss) = -acc / CTX
    // final  = mean_b loss_b  -> pre-scale and atomically accumulate
    if (lane == 0) {
        atomicAdd(out, -acc * (1.0f / (float)(CTX * BATCH)));
    }
}

extern "C" void kernel_launch(void* const* d_in, const int* in_sizes, int n_in,
                              void* d_out, int out_size) {
    const float* emb_i  = (const float*)d_in[0];
    const float* emb_o  = (const float*)d_in[1];
    const int*   iword  = (const int*)d_in[2];
    const int*   owords = (const int*)d_in[3];
    const int*   nwords = (const int*)d_in[4];
    float* out = (float*)d_out;

    sgns_zero_out<<<1, 1>>>(out);

    // one warp per batch row
    const int threads = 256;
    const int warps_per_block = threads / 32;
    const int blocks = (BATCH + warps_per_block - 1) / warps_per_block;
    sgns_kernel<<<blocks, threads>>>(emb_i, emb_o, iword, owords, nwords, out);
}

// round 2
// speedup vs baseline: 1.7067x; 1.7067x over previous
#include <cuda_runtime.h>
#include <math.h>

// Problem constants (fixed by the reference)
#define VOCAB  100000
#define DIM    128
#define BATCH  4096
#define CTX    10
#define NNEG   200   // CTX * N_NEGS
#define FULL   0xffffffffu

__device__ __forceinline__ float log_sigmoid(float x) {
    // log(sigmoid(x)) = min(x,0) - log(1 + exp(-|x|)); arg of log in (1,2] -> __logf is safe
    float ax = fabsf(x);
    return fminf(x, 0.0f) - __logf(1.0f + __expf(-ax));
}

__device__ __forceinline__ float dot4(const float4 a, const float4 b) {
    return fmaf(a.x, b.x, fmaf(a.y, b.y, fmaf(a.z, b.z, a.w * b.w)));
}

// Merge two per-lane partial-sum sets across the `bit` butterfly:
// result holds a-partials on bit-clear lanes, b-partials on bit-set lanes,
// each already reduced over the bit pair. 1 shuffle + 1 add per call.
__device__ __forceinline__ float merge2(float a, float b, int lane, int bit) {
    float send = (lane & bit) ? a : b;
    float recv = __shfl_xor_sync(FULL, send, bit);
    float keep = (lane & bit) ? b : a;
    return keep + recv;
}

// Reduce 8 independent per-lane partial sums. Returns, in each lane, the FULL
// sum of one of the 8 rows; each row's sum appears in exactly 4 lanes.
__device__ __forceinline__ float reduce8(const float p[8], int lane) {
    float m0 = merge2(p[0], p[1], lane, 16);
    float m1 = merge2(p[2], p[3], lane, 16);
    float m2 = merge2(p[4], p[5], lane, 16);
    float m3 = merge2(p[6], p[7], lane, 16);
    float n0 = merge2(m0, m1, lane, 8);
    float n1 = merge2(m2, m3, lane, 8);
    float r  = merge2(n0, n1, lane, 4);
    r += __shfl_xor_sync(FULL, r, 2);
    r += __shfl_xor_sync(FULL, r, 1);
    return r;
}

__global__ void sgns_zero_out(float* out) { out[0] = 0.0f; }

__global__ __launch_bounds__(256)
void sgns_kernel(const float* __restrict__ emb_i,
                 const float* __restrict__ emb_o,
                 const int*   __restrict__ iword,
                 const int*   __restrict__ owords,
                 const int*   __restrict__ nwords,
                 float*       __restrict__ out) {
    const int warp = (blockIdx.x * blockDim.x + threadIdx.x) >> 5;
    const int lane = threadIdx.x & 31;
    if (warp >= BATCH) return;

    // Input-word vector slice for this lane (4 floats; warp covers all 128)
    const float4 iv =
        *reinterpret_cast<const float4*>(emb_i + (size_t)iword[warp] * DIM + lane * 4);

    const int* __restrict__ ow = owords + warp * CTX;
    const int* __restrict__ nw = nwords + warp * NNEG;

    float acc4 = 0.0f;   // per-lane; each row counted 4x across the warp
    float accU = 0.0f;   // lane-uniform; each row counted once

    // ---- positives: first 8 via batched reduce, last 2 via classic butterfly ----
    {
        float p[8];
#pragma unroll
        for (int c = 0; c < 8; c++) {
            const float4 v = __ldg(
                reinterpret_cast<const float4*>(emb_o + (size_t)ow[c] * DIM) + lane);
            p[c] = dot4(iv, v);
        }
        acc4 += log_sigmoid(reduce8(p, lane));

#pragma unroll
        for (int c = 8; c < CTX; c++) {
            const float4 v = __ldg(
                reinterpret_cast<const float4*>(emb_o + (size_t)ow[c] * DIM) + lane);
            float s = dot4(iv, v);
            s += __shfl_xor_sync(FULL, s, 16);
            s += __shfl_xor_sync(FULL, s, 8);
            s += __shfl_xor_sync(FULL, s, 4);
            s += __shfl_xor_sync(FULL, s, 2);
            s += __shfl_xor_sync(FULL, s, 1);
            accU += log_sigmoid(s);
        }
    }

    // ---- negatives: 200 rows = 25 batches of 8 ----
    for (int k = 0; k < NNEG; k += 8) {
        const int4 ia = *reinterpret_cast<const int4*>(nw + k);
        const int4 ib = *reinterpret_cast<const int4*>(nw + k + 4);

        float4 v0 = __ldg(reinterpret_cast<const float4*>(emb_o + (size_t)ia.x * DIM) + lane);
        float4 v1 = __ldg(reinterpret_cast<const float4*>(emb_o + (size_t)ia.y * DIM) + lane);
        float4 v2 = __ldg(reinterpret_cast<const float4*>(emb_o + (size_t)ia.z * DIM) + lane);
        float4 v3 = __ldg(reinterpret_cast<const float4*>(emb_o + (size_t)ia.w * DIM) + lane);
        float4 v4 = __ldg(reinterpret_cast<const float4*>(emb_o + (size_t)ib.x * DIM) + lane);
        float4 v5 = __ldg(reinterpret_cast<const float4*>(emb_o + (size_t)ib.y * DIM) + lane);
        float4 v6 = __ldg(reinterpret_cast<const float4*>(emb_o + (size_t)ib.z * DIM) + lane);
        float4 v7 = __ldg(reinterpret_cast<const float4*>(emb_o + (size_t)ib.w * DIM) + lane);

        float p[8];
        p[0] = dot4(iv, v0); p[1] = dot4(iv, v1);
        p[2] = dot4(iv, v2); p[3] = dot4(iv, v3);
        p[4] = dot4(iv, v4); p[5] = dot4(iv, v5);
        p[6] = dot4(iv, v6); p[7] = dot4(iv, v7);

        acc4 += log_sigmoid(-reduce8(p, lane));
    }

    // Reduce acc4 across lanes (each row was counted 4x) and fold in accU.
    float a = acc4;
    a += __shfl_xor_sync(FULL, a, 16);
    a += __shfl_xor_sync(FULL, a, 8);
    a += __shfl_xor_sync(FULL, a, 4);
    a += __shfl_xor_sync(FULL, a, 2);
    a += __shfl_xor_sync(FULL, a, 1);
    float total = fmaf(a, 0.25f, accU);

    // loss_b = -total / CTX ; final = mean over BATCH
    if (lane == 0) {
        atomicAdd(out, -total * (1.0f / (float)(CTX * BATCH)));
    }
}

extern "C" void kernel_launch(void* const* d_in, const int* in_sizes, int n_in,
                              void* d_out, int out_size) {
    const float* emb_i  = (const float*)d_in[0];
    const float* emb_o  = (const float*)d_in[1];
    const int*   iword  = (const int*)d_in[2];
    const int*   owords = (const int*)d_in[3];
    const int*   nwords = (const int*)d_in[4];
    float* out = (float*)d_out;

    sgns_zero_out<<<1, 1>>>(out);

    const int threads = 256;
    const int warps_per_block = threads / 32;
    const int blocks = (BATCH + warps_per_block - 1) / warps_per_block;
    sgns_kernel<<<blocks, threads>>>(emb_i, emb_o, iword, owords, nwords, out);
}